// round 1
// baseline (speedup 1.0000x reference)
#include <cuda_runtime.h>
#include <cstdint>

#define B 8
#define D 128
#define T 4096
#define Q 30
#define C 1024
#define BT (B * T)          // 32768 rows
#define NOUT (B * D * T)    // 4194304 quantized elements

#define TM 64               // rows per block
#define TN 64               // codes per chunk
#define PADB 65             // ulonglong stride per k-row in Bs (bank spread)

// smem layout (bytes)
#define OFF_AS   0
#define SZ_AS    (128 * TM * 4)          // 32768
#define OFF_BS   (OFF_AS + SZ_AS)
#define SZ_BS    (128 * PADB * 8)        // 66560
#define OFF_C2   (OFF_BS + SZ_BS)
#define SZ_C2    (TN * 4)                // 256
#define OFF_RV   (OFF_C2 + SZ_C2)
#define SZ_RV    (TM * 16 * 4)           // 4096
#define OFF_RI   (OFF_RV + SZ_RV)
#define SZ_RI    (TM * 16 * 4)           // 4096
#define OFF_BI   (OFF_RI + SZ_RI)
#define SZ_BI    (TM * 4)                // 256
#define SMEM_BYTES (OFF_BI + SZ_BI)      // 108032

__device__ float  g_res[(size_t)BT * D];   // residual, row-major [bt][d]
__device__ float  g_c2[Q * C];             // per-code squared norms
__device__ double g_loss;                  // sum over steps of sum(r_new^2)

// packed fp32x2 fma: acc = a*b + acc (elementwise on both 32-bit halves)
__device__ __forceinline__ void fma2(unsigned long long& acc,
                                     unsigned long long a,
                                     unsigned long long b) {
    asm("fma.rn.f32x2 %0, %1, %2, %0;" : "+l"(acc) : "l"(a), "l"(b));
}

__device__ __forceinline__ void unpack2(unsigned long long v, float& lo, float& hi) {
    unsigned int l, h;
    asm("mov.b64 {%0, %1}, %2;" : "=r"(l), "=r"(h) : "l"(v));
    lo = __uint_as_float(l);
    hi = __uint_as_float(h);
}

// ---------------- x [B,D,T] -> g_res [B*T, D] ----------------
__global__ void k_transpose_in(const float* __restrict__ x) {
    __shared__ float tile[32][33];
    int b = blockIdx.z;
    int t0 = blockIdx.x * 32;
    int d0 = blockIdx.y * 32;
    int tx = threadIdx.x, ty = threadIdx.y;  // 32 x 8
#pragma unroll
    for (int i = 0; i < 32; i += 8) {
        int d = d0 + ty + i;
        int t = t0 + tx;
        tile[ty + i][tx] = x[((size_t)b * D + d) * T + t];
    }
    __syncthreads();
#pragma unroll
    for (int i = 0; i < 32; i += 8) {
        int t = t0 + ty + i;
        int d = d0 + tx;
        g_res[((size_t)b * T + t) * D + d] = tile[tx][ty + i];
    }
}

// ---------------- per-code squared norms ----------------
__global__ void k_c2(const float* __restrict__ cb) {
    int code = blockIdx.x * 8 + (threadIdx.x >> 5);
    int lane = threadIdx.x & 31;
    float4 v = *(const float4*)(cb + (size_t)code * D + lane * 4);
    float s = v.x * v.x + v.y * v.y + v.z * v.z + v.w * v.w;
#pragma unroll
    for (int o = 16; o; o >>= 1) s += __shfl_down_sync(0xffffffffu, s, o);
    if (lane == 0) g_c2[code] = s;
    if (blockIdx.x == 0 && threadIdx.x == 0) g_loss = 0.0;
}

// ---------------- one VQ step ----------------
__global__ __launch_bounds__(256, 2) void k_step(const float* __restrict__ cb_all, int q) {
    extern __shared__ char smem[];
    float* As = (float*)(smem + OFF_AS);                         // [128][TM] k-major
    unsigned long long* Bs = (unsigned long long*)(smem + OFF_BS); // [128][PADB] (b,b) pairs
    float* c2s = (float*)(smem + OFF_C2);
    float* rvs = (float*)(smem + OFF_RV);
    int* ris = (int*)(smem + OFF_RI);
    int* bidx = (int*)(smem + OFF_BI);

    const float* cbq = cb_all + (size_t)q * C * D;
    int tid = threadIdx.x;
    int tx = tid & 15, ty = tid >> 4;
    int rowBase = blockIdx.x * TM;

    // load residual tile into k-major smem
    for (int s = tid; s < TM * 32; s += 256) {
        int row = s >> 5, kq = s & 31;
        float4 v = *(const float4*)(g_res + ((size_t)(rowBase + row)) * D + kq * 4);
        As[(4 * kq + 0) * TM + row] = v.x;
        As[(4 * kq + 1) * TM + row] = v.y;
        As[(4 * kq + 2) * TM + row] = v.z;
        As[(4 * kq + 3) * TM + row] = v.w;
    }

    const float INF = __int_as_float(0x7f800000);
    float bestv[4] = {INF, INF, INF, INF};
    int besti[4] = {0, 0, 0, 0};

    for (int chunk = 0; chunk < C / TN; ++chunk) {
        int cBase = chunk * TN;
        __syncthreads();  // Bs reuse safe (first iter: also fences As loads)
        // load 64-code chunk as pre-broadcast pairs, k-major
        for (int s = tid; s < TN * 32; s += 256) {
            int c = s >> 5, kq = s & 31;
            float4 v = *(const float4*)(cbq + (size_t)(cBase + c) * D + kq * 4);
            unsigned long long p;
            p = __float_as_uint(v.x); p |= p << 32; Bs[(4 * kq + 0) * PADB + c] = p;
            p = __float_as_uint(v.y); p |= p << 32; Bs[(4 * kq + 1) * PADB + c] = p;
            p = __float_as_uint(v.z); p |= p << 32; Bs[(4 * kq + 2) * PADB + c] = p;
            p = __float_as_uint(v.w); p |= p << 32; Bs[(4 * kq + 3) * PADB + c] = p;
        }
        if (tid < TN) c2s[tid] = g_c2[q * C + cBase + tid];
        __syncthreads();

        // 4 rows (pairs) x 4 interleaved cols accumulators
        unsigned long long acc[2][4];
#pragma unroll
        for (int rp = 0; rp < 2; ++rp)
#pragma unroll
            for (int j = 0; j < 4; ++j) acc[rp][j] = 0ull;

        const float* ap = As + 4 * ty;
        const unsigned long long* bp = Bs + tx;
#pragma unroll 8
        for (int k = 0; k < D; ++k) {
            ulonglong2 a2 = *(const ulonglong2*)(ap + (size_t)k * TM);
            unsigned long long b0 = bp[(size_t)k * PADB];
            unsigned long long b1 = bp[(size_t)k * PADB + 16];
            unsigned long long b2 = bp[(size_t)k * PADB + 32];
            unsigned long long b3 = bp[(size_t)k * PADB + 48];
            fma2(acc[0][0], a2.x, b0);
            fma2(acc[1][0], a2.y, b0);
            fma2(acc[0][1], a2.x, b1);
            fma2(acc[1][1], a2.y, b1);
            fma2(acc[0][2], a2.x, b2);
            fma2(acc[1][2], a2.y, b2);
            fma2(acc[0][3], a2.x, b3);
            fma2(acc[1][3], a2.y, b3);
        }

        // score = c2 - 2*dot ; keep running (val, idx) min per row
#pragma unroll
        for (int j = 0; j < 4; ++j) {
            int cg = cBase + tx + 16 * j;
            float c2v = c2s[tx + 16 * j];
            float d0, d1, d2, d3;
            unpack2(acc[0][j], d0, d1);
            unpack2(acc[1][j], d2, d3);
            float v0 = fmaf(-2.f, d0, c2v);
            float v1 = fmaf(-2.f, d1, c2v);
            float v2 = fmaf(-2.f, d2, c2v);
            float v3 = fmaf(-2.f, d3, c2v);
            if (v0 < bestv[0] || (v0 == bestv[0] && cg < besti[0])) { bestv[0] = v0; besti[0] = cg; }
            if (v1 < bestv[1] || (v1 == bestv[1] && cg < besti[1])) { bestv[1] = v1; besti[1] = cg; }
            if (v2 < bestv[2] || (v2 == bestv[2] && cg < besti[2])) { bestv[2] = v2; besti[2] = cg; }
            if (v3 < bestv[3] || (v3 == bestv[3] && cg < besti[3])) { bestv[3] = v3; besti[3] = cg; }
        }
    }
    __syncthreads();
#pragma unroll
    for (int rr = 0; rr < 4; ++rr) {
        rvs[(4 * ty + rr) * 16 + tx] = bestv[rr];
        ris[(4 * ty + rr) * 16 + tx] = besti[rr];
    }
    __syncthreads();
    if (tid < TM) {
        float bv = rvs[tid * 16];
        int bi = ris[tid * 16];
#pragma unroll
        for (int j = 1; j < 16; ++j) {
            float v = rvs[tid * 16 + j];
            int i2 = ris[tid * 16 + j];
            if (v < bv || (v == bv && i2 < bi)) { bv = v; bi = i2; }
        }
        bidx[tid] = bi;
    }
    __syncthreads();

    // residual update + loss partial
    float lsum = 0.f;
    for (int e = tid; e < TM * D; e += 256) {
        int row = e >> 7, d = e & 127;
        float cv = cbq[(size_t)bidx[row] * D + d];
        float nv = As[d * TM + row] - cv;
        g_res[((size_t)(rowBase + row)) * D + d] = nv;
        lsum += nv * nv;
    }
#pragma unroll
    for (int o = 16; o; o >>= 1) lsum += __shfl_down_sync(0xffffffffu, lsum, o);
    __syncthreads();  // done reading rvs; reuse as warp-partial scratch
    if ((tid & 31) == 0) rvs[tid >> 5] = lsum;
    __syncthreads();
    if (tid == 0) {
        float tot = 0.f;
#pragma unroll
        for (int w = 0; w < 8; ++w) tot += rvs[w];
        atomicAdd(&g_loss, (double)tot);
    }
}

// ---------------- out[B,D,T] = x - residual_final^T ; loss ----------------
__global__ void k_finalize(const float* __restrict__ x, float* __restrict__ out, int out_size) {
    __shared__ float tile[32][33];
    int b = blockIdx.z;
    int t0 = blockIdx.x * 32;
    int d0 = blockIdx.y * 32;
    int tx = threadIdx.x, ty = threadIdx.y;
#pragma unroll
    for (int i = 0; i < 32; i += 8) {
        int t = t0 + ty + i;
        int d = d0 + tx;
        tile[ty + i][tx] = g_res[((size_t)b * T + t) * D + d];
    }
    __syncthreads();
#pragma unroll
    for (int i = 0; i < 32; i += 8) {
        int d = d0 + ty + i;
        int t = t0 + tx;
        size_t idx = ((size_t)b * D + d) * T + t;
        out[idx] = x[idx] - tile[tx][ty + i];
    }
    if (blockIdx.x == 0 && blockIdx.y == 0 && blockIdx.z == 0 && tx == 0 && ty == 0 &&
        out_size > NOUT) {
        out[NOUT] = (float)(g_loss / (double)((size_t)BT * D));
    }
}

extern "C" void kernel_launch(void* const* d_in, const int* in_sizes, int n_in,
                              void* d_out, int out_size) {
    const float* x = (const float*)d_in[0];
    const float* cb = (const float*)d_in[1];
    float* out = (float*)d_out;

    cudaFuncSetAttribute(k_step, cudaFuncAttributeMaxDynamicSharedMemorySize, SMEM_BYTES);

    dim3 tb(32, 8);
    dim3 tg(T / 32, D / 32, B);
    k_transpose_in<<<tg, tb>>>(x);
    k_c2<<<(Q * C) / 8, 256>>>(cb);
    for (int q = 0; q < Q; ++q) {
        k_step<<<BT / TM, 256, SMEM_BYTES>>>(cb, q);
    }
    k_finalize<<<tg, tb>>>(x, out, out_size);
}

// round 3
// speedup vs baseline: 1.5899x; 1.5899x over previous
#include <cuda_runtime.h>
#include <cstdint>

#define B_ 8
#define D_ 128
#define T_ 4096
#define Q_ 30
#define C_ 1024
#define BT_ (B_ * T_)
#define NOUT (B_ * D_ * T_)

#define TM 64
#define TN 64
#define NCHUNK (C_ / TN)

// smem layout (bytes)
#define OFF_AS 0
#define SZ_AS (128 * 64 * 4)            // 32768  residual tile, k-major [d][row]
#define OFF_BS (OFF_AS + SZ_AS)
#define SZ_BS (128 * 64 * 8)            // 65536  codebook chunk, (b,b) pairs, XOR-swizzled
#define OFF_C2 (OFF_BS + SZ_BS)
#define SZ_C2 (64 * 4)
#define OFF_RV (OFF_C2 + SZ_C2)
#define SZ_RV (64 * 16 * 4)
#define OFF_RI (OFF_RV + SZ_RV)
#define SZ_RI (64 * 16 * 4)
#define OFF_BI (OFF_RI + SZ_RI)
#define SZ_BI (64 * 4)
#define OFF_LR (OFF_BI + SZ_BI)
#define SZ_LR (4 * 8)
#define SMEM_BYTES (OFF_LR + SZ_LR)     // ~104.5KB; x2 CTAs = 209KB/SM

__device__ float g_c2[Q_ * C_];
__device__ double g_loss;

__device__ __forceinline__ void fma2(unsigned long long& acc,
                                     unsigned long long a,
                                     unsigned long long b) {
    asm("fma.rn.f32x2 %0, %1, %2, %0;" : "+l"(acc) : "l"(a), "l"(b));
}

__device__ __forceinline__ void unpack2(unsigned long long v, float& lo, float& hi) {
    unsigned int l, h;
    asm("mov.b64 {%0, %1}, %2;" : "=r"(l), "=r"(h) : "l"(v));
    lo = __uint_as_float(l);
    hi = __uint_as_float(h);
}

// per-code squared norms + zero the loss accumulator
__global__ void k_c2(const float* __restrict__ cb) {
    int code = blockIdx.x * 8 + (threadIdx.x >> 5);
    int lane = threadIdx.x & 31;
    float4 v = *(const float4*)(cb + (size_t)code * D_ + lane * 4);
    float s = v.x * v.x + v.y * v.y + v.z * v.z + v.w * v.w;
#pragma unroll
    for (int o = 16; o; o >>= 1) s += __shfl_down_sync(0xffffffffu, s, o);
    if (lane == 0) g_c2[code] = s;
    if (blockIdx.x == 0 && threadIdx.x == 0) g_loss = 0.0;
}

// all 30 VQ steps fused; each block owns 64 (b,t) rows resident in smem
__global__ __launch_bounds__(128, 2) void k_vq(const float* __restrict__ x,
                                               const float* __restrict__ cb_all,
                                               float* __restrict__ out) {
    extern __shared__ char smem[];
    float* As = (float*)(smem + OFF_AS);
    unsigned long long* Bs = (unsigned long long*)(smem + OFF_BS);
    float* Qs = (float*)(smem + OFF_BS);   // alias: staging for chosen code rows (128x65 floats)
    float* c2s = (float*)(smem + OFF_C2);
    float* rvs = (float*)(smem + OFF_RV);
    int* ris = (int*)(smem + OFF_RI);
    int* bidx = (int*)(smem + OFF_BI);
    double* lred = (double*)(smem + OFF_LR);

    const int tid = threadIdx.x;
    const int tx = tid & 15;
    const int ty = tid >> 4;              // 0..7, 8 rows each
    const int txx = 2 * tx;
    const int bt0 = blockIdx.x * TM;
    const int b = bt0 / T_;
    const int t0 = bt0 % T_;
    const float* xb = x + (size_t)b * D_ * T_ + t0;

    // load residual tile: As[d*64 + t] = x[b, d, t0+t]   (coalesced, conflict-free)
    for (int i = 0; i < 64; ++i) {
        int idx = i * 128 + tid;
        int d = idx >> 6, tc = idx & 63;
        As[d * 64 + tc] = xb[(size_t)d * T_ + tc];
    }

    double dloss = 0.0;

    for (int q = 0; q < Q_; ++q) {
        const float* cbq = cb_all + (size_t)q * C_ * D_;
        const float INF = __int_as_float(0x7f800000);
        float bestv[8];
        int besti[8];
#pragma unroll
        for (int r = 0; r < 8; ++r) { bestv[r] = INF; besti[r] = 0; }

        for (int ch = 0; ch < NCHUNK; ++ch) {
            const int cBase = ch * TN;
            __syncthreads();  // Bs/Qs reuse + As-update ordering
            // load 64-code chunk: warp-per-code coalesced read, pre-broadcast
            // (b,b) pairs, XOR-swizzled columns (2-way store conflict max)
#pragma unroll 4
            for (int it = 0; it < 16; ++it) {
                int s = it * 128 + tid;
                int c = s >> 5, kq = s & 31;
                float4 v = *(const float4*)(cbq + (size_t)(cBase + c) * D_ + kq * 4);
                int j = c >> 4, t = c & 15;
                int sl = (j < 2) ? (2 * t + j) : (32 + 2 * t + (j - 2));
                int m = (kq & 15) * 2;
                int col = (sl & 32) + ((sl & 31) ^ m);
                unsigned long long p;
                p = __float_as_uint(v.x); p |= p << 32; Bs[(4 * kq + 0) * 64 + col] = p;
                p = __float_as_uint(v.y); p |= p << 32; Bs[(4 * kq + 1) * 64 + col] = p;
                p = __float_as_uint(v.z); p |= p << 32; Bs[(4 * kq + 2) * 64 + col] = p;
                p = __float_as_uint(v.w); p |= p << 32; Bs[(4 * kq + 3) * 64 + col] = p;
            }
            if (tid < 64) c2s[tid] = g_c2[q * C_ + cBase + tid];
            __syncthreads();

            unsigned long long acc[4][4];
#pragma unroll
            for (int rp = 0; rp < 4; ++rp)
#pragma unroll
                for (int j = 0; j < 4; ++j) acc[rp][j] = 0ull;

            // A rows for this thread: floats [8ty .. 8ty+7] of each k-row.
            // One As k-row = 64 floats = 16 ulonglong2.
            const ulonglong2* pA = (const ulonglong2*)As + 2 * ty;
#pragma unroll 8
            for (int k = 0; k < 128; ++k) {
                int m = ((k >> 2) & 15) * 2;
                const unsigned long long* bk = Bs + k * 64;
                ulonglong2 a01 = pA[k * 16];        // rows 8ty..8ty+3
                ulonglong2 a23 = pA[k * 16 + 1];    // rows 8ty+4..8ty+7
                ulonglong2 b01 = *(const ulonglong2*)(bk + (txx ^ m));        // cols j=0,1
                ulonglong2 b23 = *(const ulonglong2*)(bk + 32 + (txx ^ m));   // cols j=2,3
                fma2(acc[0][0], a01.x, b01.x); fma2(acc[1][0], a01.y, b01.x);
                fma2(acc[2][0], a23.x, b01.x); fma2(acc[3][0], a23.y, b01.x);
                fma2(acc[0][1], a01.x, b01.y); fma2(acc[1][1], a01.y, b01.y);
                fma2(acc[2][1], a23.x, b01.y); fma2(acc[3][1], a23.y, b01.y);
                fma2(acc[0][2], a01.x, b23.x); fma2(acc[1][2], a01.y, b23.x);
                fma2(acc[2][2], a23.x, b23.x); fma2(acc[3][2], a23.y, b23.x);
                fma2(acc[0][3], a01.x, b23.y); fma2(acc[1][3], a01.y, b23.y);
                fma2(acc[2][3], a23.x, b23.y); fma2(acc[3][3], a23.y, b23.y);
            }

            // scores: c2 - 2*dot, running (val, idx) min with first-min tie-break
#pragma unroll
            for (int j = 0; j < 4; ++j) {
                int cg = cBase + tx + 16 * j;
                float c2v = c2s[tx + 16 * j];
#pragma unroll
                for (int rp = 0; rp < 4; ++rp) {
                    float lo, hi;
                    unpack2(acc[rp][j], lo, hi);
                    float v0 = fmaf(-2.f, lo, c2v);
                    float v1 = fmaf(-2.f, hi, c2v);
                    int r0 = 2 * rp, r1 = 2 * rp + 1;
                    if (v0 < bestv[r0] || (v0 == bestv[r0] && cg < besti[r0])) { bestv[r0] = v0; besti[r0] = cg; }
                    if (v1 < bestv[r1] || (v1 == bestv[r1] && cg < besti[r1])) { bestv[r1] = v1; besti[r1] = cg; }
                }
            }
        }

        // per-row argmin across the 16 tx columns
#pragma unroll
        for (int r = 0; r < 8; ++r) {
            rvs[(8 * ty + r) * 16 + tx] = bestv[r];
            ris[(8 * ty + r) * 16 + tx] = besti[r];
        }
        __syncthreads();
        if (tid < 64) {
            float bv = rvs[tid * 16];
            int bi = ris[tid * 16];
#pragma unroll
            for (int jj = 1; jj < 16; ++jj) {
                float v = rvs[tid * 16 + jj];
                int i2 = ris[tid * 16 + jj];
                if (v < bv || (v == bv && i2 < bi)) { bv = v; bi = i2; }
            }
            bidx[tid] = bi;
        }
        __syncthreads();

        // stage chosen code rows coalesced into Qs (transposed, pad 65 -> conflict-free)
#pragma unroll 4
        for (int r = 0; r < 64; ++r) {
            Qs[tid * 65 + r] = cbq[(size_t)bidx[r] * D_ + tid];
        }
        __syncthreads();

        // residual update in smem + loss partial
        {
            int row = tid & 63;
            int dbase = (tid >> 6) * 64;
            float ls = 0.f;
#pragma unroll 8
            for (int dd = 0; dd < 64; ++dd) {
                int d = dbase + dd;
                float nv = As[d * 64 + row] - Qs[d * 65 + row];
                As[d * 64 + row] = nv;
                ls += nv * nv;
            }
            dloss += (double)ls;
        }
        // next chunk-top __syncthreads orders As writes / Qs overwrite
    }

    __syncthreads();
    // quantized = x - residual_final, written straight in [B,D,T] layout
    for (int i = 0; i < 64; ++i) {
        int idx = i * 128 + tid;
        int d = idx >> 6, tc = idx & 63;
        size_t gi = (size_t)d * T_ + tc;
        out[(size_t)b * D_ * T_ + t0 + gi] = xb[gi] - As[d * 64 + tc];
    }

    // loss reduce: warp shuffle -> smem -> one atomicAdd per block
    double v = dloss;
#pragma unroll
    for (int o = 16; o; o >>= 1) v += __shfl_down_sync(0xffffffffu, v, o);
    if ((tid & 31) == 0) lred[tid >> 5] = v;
    __syncthreads();
    if (tid == 0) atomicAdd(&g_loss, lred[0] + lred[1] + lred[2] + lred[3]);
}

__global__ void k_loss(float* __restrict__ out, int out_size) {
    if (out_size > NOUT) out[NOUT] = (float)(g_loss / (double)((size_t)BT_ * D_));
}

extern "C" void kernel_launch(void* const* d_in, const int* in_sizes, int n_in,
                              void* d_out, int out_size) {
    const float* x = (const float*)d_in[0];
    const float* cb = (const float*)d_in[1];
    float* out = (float*)d_out;

    cudaFuncSetAttribute(k_vq, cudaFuncAttributeMaxDynamicSharedMemorySize, SMEM_BYTES);

    k_c2<<<(Q_ * C_) / 8, 256>>>(cb);
    k_vq<<<BT_ / TM, 128, SMEM_BYTES>>>(x, cb, out);
    k_loss<<<1, 1>>>(out, out_size);
}

// round 4
// speedup vs baseline: 1.6214x; 1.0198x over previous
#include <cuda_runtime.h>
#include <cstdint>

#define B_ 8
#define D_ 128
#define T_ 4096
#define Q_ 30
#define C_ 1024
#define BT_ (B_ * T_)
#define NOUT (B_ * D_ * T_)

#define TM 64
#define TN 64
#define NCHUNK (C_ / TN)

// smem layout (bytes)
#define OFF_AS 0
#define SZ_AS (128 * 64 * 4)            // 32768  residual tile, k-major [d][row]
#define OFF_BS (OFF_AS + SZ_AS)
#define SZ_BS (128 * 64 * 8)            // 65536  codebook chunk, (b,b) pairs, k-major
#define OFF_C2 (OFF_BS + SZ_BS)
#define SZ_C2 (64 * 4)
#define OFF_RV (OFF_C2 + SZ_C2)
#define SZ_RV (64 * 16 * 4)
#define OFF_RI (OFF_RV + SZ_RV)
#define SZ_RI (64 * 16 * 4)
#define OFF_BI (OFF_RI + SZ_RI)
#define SZ_BI (64 * 4)
#define OFF_LR (OFF_BI + SZ_BI)
#define SZ_LR (4 * 8)
#define SMEM_BYTES (OFF_LR + SZ_LR)     // ~104.5KB; x2 CTAs = 209KB/SM

__device__ float g_c2[Q_ * C_];
__device__ double g_loss;
// pre-transposed, pre-broadcast codebook: [q][k][c] of (b,b) 8-byte pairs
__device__ unsigned long long g_cbT[(size_t)Q_ * D_ * C_];

__device__ __forceinline__ void fma2(unsigned long long& acc,
                                     unsigned long long a,
                                     unsigned long long b) {
    asm("fma.rn.f32x2 %0, %1, %2, %0;" : "+l"(acc) : "l"(a), "l"(b));
}

__device__ __forceinline__ void unpack2(unsigned long long v, float& lo, float& hi) {
    unsigned int l, h;
    asm("mov.b64 {%0, %1}, %2;" : "=r"(l), "=r"(h) : "l"(v));
    lo = __uint_as_float(l);
    hi = __uint_as_float(h);
}

// ---- prep: cb [q][c][d] -> g_cbT [q][d][c] broadcast pairs (one-time) ----
__global__ void k_prep(const float* __restrict__ cb) {
    __shared__ float tile[32][33];
    int q = blockIdx.z;
    int c0 = blockIdx.x * 32;
    int d0 = blockIdx.y * 32;
    int tx = threadIdx.x, ty = threadIdx.y;  // 32 x 8
#pragma unroll
    for (int i = 0; i < 32; i += 8) {
        tile[ty + i][tx] = cb[((size_t)q * C_ + c0 + ty + i) * D_ + d0 + tx];
    }
    __syncthreads();
#pragma unroll
    for (int i = 0; i < 32; i += 8) {
        unsigned long long p = __float_as_uint(tile[tx][ty + i]);
        p |= p << 32;
        g_cbT[((size_t)q * D_ + d0 + ty + i) * C_ + c0 + tx] = p;
    }
}

// per-code squared norms + zero the loss accumulator
__global__ void k_c2(const float* __restrict__ cb) {
    int code = blockIdx.x * 8 + (threadIdx.x >> 5);
    int lane = threadIdx.x & 31;
    float4 v = *(const float4*)(cb + (size_t)code * D_ + lane * 4);
    float s = v.x * v.x + v.y * v.y + v.z * v.z + v.w * v.w;
#pragma unroll
    for (int o = 16; o; o >>= 1) s += __shfl_down_sync(0xffffffffu, s, o);
    if (lane == 0) g_c2[code] = s;
    if (blockIdx.x == 0 && threadIdx.x == 0) g_loss = 0.0;
}

// all 30 VQ steps fused; each block owns 64 (b,t) rows resident in smem
__global__ __launch_bounds__(128, 2) void k_vq(const float* __restrict__ x,
                                               const float* __restrict__ cb_all,
                                               float* __restrict__ out) {
    extern __shared__ char smem[];
    float* As = (float*)(smem + OFF_AS);
    unsigned long long* Bs = (unsigned long long*)(smem + OFF_BS);
    float* Qs = (float*)(smem + OFF_BS);   // alias: staging for chosen code rows (128x65 floats)
    float* c2s = (float*)(smem + OFF_C2);
    float* rvs = (float*)(smem + OFF_RV);
    int* ris = (int*)(smem + OFF_RI);
    int* bidx = (int*)(smem + OFF_BI);
    double* lred = (double*)(smem + OFF_LR);

    const int tid = threadIdx.x;
    const int tx = tid & 15;
    const int ty = tid >> 4;              // 0..7, 8 rows each
    const int bt0 = blockIdx.x * TM;
    const int b = bt0 / T_;
    const int t0 = bt0 % T_;
    const float* xb = x + (size_t)b * D_ * T_ + t0;

    // load residual tile: As[d*64 + t] = x[b, d, t0+t]   (coalesced, conflict-free)
    for (int i = 0; i < 64; ++i) {
        int idx = i * 128 + tid;
        int d = idx >> 6, tc = idx & 63;
        As[d * 64 + tc] = xb[(size_t)d * T_ + tc];
    }

    double dloss = 0.0;

    for (int q = 0; q < Q_; ++q) {
        const float* cbq = cb_all + (size_t)q * C_ * D_;
        const unsigned long long* cbTq = g_cbT + (size_t)q * D_ * C_;
        const float INF = __int_as_float(0x7f800000);
        float bestv[8];
        int besti[8];
#pragma unroll
        for (int r = 0; r < 8; ++r) { bestv[r] = INF; besti[r] = 0; }

        for (int ch = 0; ch < NCHUNK; ++ch) {
            const int cBase = ch * TN;
            __syncthreads();  // Bs/Qs reuse + As-update ordering
            // chunk load: warp = one k row; dense LDG.128 -> dense STS.128,
            // fully conflict-free, no swizzle
#pragma unroll 8
            for (int it = 0; it < 32; ++it) {
                int s = it * 128 + tid;
                int k = s >> 5, lane = s & 31;
                ulonglong2 v = ((const ulonglong2*)(cbTq + (size_t)k * C_ + cBase))[lane];
                ((ulonglong2*)(Bs + k * 64))[lane] = v;
            }
            if (tid < 64) c2s[tid] = g_c2[q * C_ + cBase + tid];
            __syncthreads();

            unsigned long long acc[4][4];
#pragma unroll
            for (int rp = 0; rp < 4; ++rp)
#pragma unroll
                for (int j = 0; j < 4; ++j) acc[rp][j] = 0ull;

            // A rows: floats [8ty..8ty+7] of each k-row (row = 64 floats = 16 ull2)
            // B cols: codes {2tx, 2tx+1, 2tx+32, 2tx+33} (row = 64 ull = 32 ull2)
            const ulonglong2* pA = (const ulonglong2*)As + 2 * ty;
            const ulonglong2* pB = (const ulonglong2*)Bs + tx;
#pragma unroll 8
            for (int k = 0; k < 128; ++k) {
                ulonglong2 a01 = pA[k * 16];        // rows 8ty..8ty+3
                ulonglong2 a23 = pA[k * 16 + 1];    // rows 8ty+4..8ty+7
                ulonglong2 b01 = pB[k * 32];        // codes 2tx, 2tx+1
                ulonglong2 b23 = pB[k * 32 + 16];   // codes 2tx+32, 2tx+33
                fma2(acc[0][0], a01.x, b01.x); fma2(acc[1][0], a01.y, b01.x);
                fma2(acc[2][0], a23.x, b01.x); fma2(acc[3][0], a23.y, b01.x);
                fma2(acc[0][1], a01.x, b01.y); fma2(acc[1][1], a01.y, b01.y);
                fma2(acc[2][1], a23.x, b01.y); fma2(acc[3][1], a23.y, b01.y);
                fma2(acc[0][2], a01.x, b23.x); fma2(acc[1][2], a01.y, b23.x);
                fma2(acc[2][2], a23.x, b23.x); fma2(acc[3][2], a23.y, b23.x);
                fma2(acc[0][3], a01.x, b23.y); fma2(acc[1][3], a01.y, b23.y);
                fma2(acc[2][3], a23.x, b23.y); fma2(acc[3][3], a23.y, b23.y);
            }

            // scores: c2 - 2*dot, running (val, idx) min with first-min tie-break
            const int cols[4] = {2 * tx, 2 * tx + 1, 2 * tx + 32, 2 * tx + 33};
#pragma unroll
            for (int j = 0; j < 4; ++j) {
                int cg = cBase + cols[j];
                float c2v = c2s[cols[j]];
#pragma unroll
                for (int rp = 0; rp < 4; ++rp) {
                    float lo, hi;
                    unpack2(acc[rp][j], lo, hi);
                    float v0 = fmaf(-2.f, lo, c2v);
                    float v1 = fmaf(-2.f, hi, c2v);
                    int r0 = 2 * rp, r1 = 2 * rp + 1;
                    if (v0 < bestv[r0] || (v0 == bestv[r0] && cg < besti[r0])) { bestv[r0] = v0; besti[r0] = cg; }
                    if (v1 < bestv[r1] || (v1 == bestv[r1] && cg < besti[r1])) { bestv[r1] = v1; besti[r1] = cg; }
                }
            }
        }

        // per-row argmin across the 16 tx columns
#pragma unroll
        for (int r = 0; r < 8; ++r) {
            rvs[(8 * ty + r) * 16 + tx] = bestv[r];
            ris[(8 * ty + r) * 16 + tx] = besti[r];
        }
        __syncthreads();
        if (tid < 64) {
            float bv = rvs[tid * 16];
            int bi = ris[tid * 16];
#pragma unroll
            for (int jj = 1; jj < 16; ++jj) {
                float v = rvs[tid * 16 + jj];
                int i2 = ris[tid * 16 + jj];
                if (v < bv || (v == bv && i2 < bi)) { bv = v; bi = i2; }
            }
            bidx[tid] = bi;
        }
        __syncthreads();

        // stage chosen code rows coalesced into Qs (transposed, pad 65 -> conflict-free)
#pragma unroll 4
        for (int r = 0; r < 64; ++r) {
            Qs[tid * 65 + r] = cbq[(size_t)bidx[r] * D_ + tid];
        }
        __syncthreads();

        // residual update in smem + loss partial
        {
            int row = tid & 63;
            int dbase = (tid >> 6) * 64;
            float ls = 0.f;
#pragma unroll 8
            for (int dd = 0; dd < 64; ++dd) {
                int d = dbase + dd;
                float nv = As[d * 64 + row] - Qs[d * 65 + row];
                As[d * 64 + row] = nv;
                ls += nv * nv;
            }
            dloss += (double)ls;
        }
        // next chunk-top __syncthreads orders As writes / Qs overwrite
    }

    __syncthreads();
    // quantized = x - residual_final, written straight in [B,D,T] layout
    for (int i = 0; i < 64; ++i) {
        int idx = i * 128 + tid;
        int d = idx >> 6, tc = idx & 63;
        size_t gi = (size_t)d * T_ + tc;
        out[(size_t)b * D_ * T_ + t0 + gi] = xb[gi] - As[d * 64 + tc];
    }

    // loss reduce: warp shuffle -> smem -> one atomicAdd per block
    double v = dloss;
#pragma unroll
    for (int o = 16; o; o >>= 1) v += __shfl_down_sync(0xffffffffu, v, o);
    if ((tid & 31) == 0) lred[tid >> 5] = v;
    __syncthreads();
    if (tid == 0) atomicAdd(&g_loss, lred[0] + lred[1] + lred[2] + lred[3]);
}

__global__ void k_loss(float* __restrict__ out, int out_size) {
    if (out_size > NOUT) out[NOUT] = (float)(g_loss / (double)((size_t)BT_ * D_));
}

extern "C" void kernel_launch(void* const* d_in, const int* in_sizes, int n_in,
                              void* d_out, int out_size) {
    const float* x = (const float*)d_in[0];
    const float* cb = (const float*)d_in[1];
    float* out = (float*)d_out;

    cudaFuncSetAttribute(k_vq, cudaFuncAttributeMaxDynamicSharedMemorySize, SMEM_BYTES);

    dim3 ptb(32, 8);
    dim3 ptg(C_ / 32, D_ / 32, Q_);
    k_prep<<<ptg, ptb>>>(cb);
    k_c2<<<(Q_ * C_) / 8, 256>>>(cb);
    k_vq<<<BT_ / TM, 128, SMEM_BYTES>>>(x, cb, out);
    k_loss<<<1, 1>>>(out, out_size);
}

// round 5
// speedup vs baseline: 1.7623x; 1.0869x over previous
#include <cuda_runtime.h>
#include <cstdint>

#define B_ 8
#define D_ 128
#define T_ 4096
#define Q_ 30
#define C_ 1024
#define BT_ (B_ * T_)
#define NOUT (B_ * D_ * T_)

#define TM 128
#define TN 64
#define NCHUNK (C_ / TN)
#define THREADS 256

// smem layout (bytes)
#define OFF_AS 0
#define SZ_AS (128 * 128 * 4)           // 65536  residual tile, k-major [d][row]
#define OFF_B0 (OFF_AS + SZ_AS)         // 65536  Bs buffer 0 (64KB)
#define SZ_B (128 * 64 * 8)             // 65536
#define OFF_B1 (OFF_B0 + SZ_B)          // 131072 Bs buffer 1 (64KB)
#define OFF_C2 (OFF_B1 + SZ_B)          // 196608
#define SZ_C2 (C_ * 4)                  // 4096
#define OFF_BI (OFF_C2 + SZ_C2)         // 200704
#define SZ_BI (TM * 4)                  // 512
#define OFF_LR (OFF_BI + SZ_BI)         // 201216
#define SZ_LR (8 * 8)
#define SMEM_BYTES (OFF_LR + SZ_LR)     // 201280
// aliases inside the B0/B1 region (used only after all chunk compute of a q):
#define OFF_RV OFF_B0                   // 128*16*4 = 8192
#define OFF_RI (OFF_B0 + 8192)          // 8192
#define OFF_QS (OFF_B0 + 16384)         // 128*129*4 = 66048, ends at 82432 < 131072

__device__ float g_c2[Q_ * C_];
__device__ double g_loss;
// pre-transposed, pre-broadcast codebook: [q][k][c] of (b,b) 8-byte pairs
__device__ unsigned long long g_cbT[(size_t)Q_ * D_ * C_];

__device__ __forceinline__ void fma2(unsigned long long& acc,
                                     unsigned long long a,
                                     unsigned long long b) {
    asm("fma.rn.f32x2 %0, %1, %2, %0;" : "+l"(acc) : "l"(a), "l"(b));
}

__device__ __forceinline__ void unpack2(unsigned long long v, float& lo, float& hi) {
    unsigned int l, h;
    asm("mov.b64 {%0, %1}, %2;" : "=r"(l), "=r"(h) : "l"(v));
    lo = __uint_as_float(l);
    hi = __uint_as_float(h);
}

__device__ __forceinline__ void cp16(uint32_t saddr, const void* g) {
    asm volatile("cp.async.cg.shared.global [%0], [%1], 16;\n" ::"r"(saddr), "l"(g));
}
#define CP_COMMIT asm volatile("cp.async.commit_group;\n" ::: "memory")
#define CP_WAIT0 asm volatile("cp.async.wait_group 0;\n" ::: "memory")

// ---- prep: cb [q][c][d] -> g_cbT [q][d][c] broadcast pairs (one-time) ----
__global__ void k_prep(const float* __restrict__ cb) {
    __shared__ float tile[32][33];
    int q = blockIdx.z;
    int c0 = blockIdx.x * 32;
    int d0 = blockIdx.y * 32;
    int tx = threadIdx.x, ty = threadIdx.y;  // 32 x 8
#pragma unroll
    for (int i = 0; i < 32; i += 8) {
        tile[ty + i][tx] = cb[((size_t)q * C_ + c0 + ty + i) * D_ + d0 + tx];
    }
    __syncthreads();
#pragma unroll
    for (int i = 0; i < 32; i += 8) {
        unsigned long long p = __float_as_uint(tile[tx][ty + i]);
        p |= p << 32;
        g_cbT[((size_t)q * D_ + d0 + ty + i) * C_ + c0 + tx] = p;
    }
}

// per-code squared norms + zero the loss accumulator
__global__ void k_c2(const float* __restrict__ cb) {
    int code = blockIdx.x * 8 + (threadIdx.x >> 5);
    int lane = threadIdx.x & 31;
    float4 v = *(const float4*)(cb + (size_t)code * D_ + lane * 4);
    float s = v.x * v.x + v.y * v.y + v.z * v.z + v.w * v.w;
#pragma unroll
    for (int o = 16; o; o >>= 1) s += __shfl_down_sync(0xffffffffu, s, o);
    if (lane == 0) g_c2[code] = s;
    if (blockIdx.x == 0 && threadIdx.x == 0) g_loss = 0.0;
}

// all 30 VQ steps fused; each block owns 128 (b,t) rows resident in smem.
// Double-buffered codebook chunks via cp.async overlap loads with FMA.
__global__ __launch_bounds__(THREADS, 1) void k_vq(const float* __restrict__ x,
                                                   const float* __restrict__ cb_all,
                                                   float* __restrict__ out) {
    extern __shared__ char smem[];
    float* As = (float*)(smem + OFF_AS);
    float* c2s = (float*)(smem + OFF_C2);
    float* rvs = (float*)(smem + OFF_RV);
    int* ris = (int*)(smem + OFF_RI);
    float* Qs = (float*)(smem + OFF_QS);
    int* bidx = (int*)(smem + OFF_BI);
    double* lred = (double*)(smem + OFF_LR);

    const int tid = threadIdx.x;
    const int tx = tid & 15;
    const int ty = tid >> 4;                // 0..15, 8 rows each
    const int bt0 = blockIdx.x * TM;
    const int b = bt0 / T_;
    const int t0 = bt0 % T_;
    const float* xb = x + (size_t)b * D_ * T_ + t0;

    uint32_t sB[2];
    sB[0] = (uint32_t)__cvta_generic_to_shared(smem + OFF_B0);
    sB[1] = (uint32_t)__cvta_generic_to_shared(smem + OFF_B1);

    // load residual tile: As[d*128 + t] = x[b, d, t0+t] (coalesced, conflict-free)
    for (int i = 0; i < 64; ++i) {
        int idx = i * THREADS + tid;
        int d = idx >> 7, tc = idx & 127;
        As[d * 128 + tc] = xb[(size_t)d * T_ + tc];
    }

    double dloss = 0.0;

    for (int q = 0; q < Q_; ++q) {
        const float* cbq = cb_all + (size_t)q * C_ * D_;
        const unsigned long long* cbTq = g_cbT + (size_t)q * D_ * C_;

        // c2 for all 1024 codes of this step
        for (int i = tid; i < C_; i += THREADS) c2s[i] = g_c2[q * C_ + i];

        // prefetch chunk 0 -> buf0 (64KB = 4096 x 16B units)
#pragma unroll 4
        for (int it = 0; it < 16; ++it) {
            int u = it * THREADS + tid;
            cp16(sB[0] + u * 16,
                 (const void*)(cbTq + (size_t)(u >> 5) * C_ + 0 + (size_t)(u & 31) * 2));
        }
        CP_COMMIT;

        const float INF = __int_as_float(0x7f800000);
        float bestv[8];
        int besti[8];
#pragma unroll
        for (int r = 0; r < 8; ++r) { bestv[r] = INF; besti[r] = 0; }

        for (int ch = 0; ch < NCHUNK; ++ch) {
            CP_WAIT0;
            __syncthreads();  // chunk ch resident; all threads past chunk ch-1 compute

            if (ch + 1 < NCHUNK) {  // prefetch next chunk into the other buffer
                int nb = (ch + 1) & 1;
                int cB = (ch + 1) * TN;
#pragma unroll 4
                for (int it = 0; it < 16; ++it) {
                    int u = it * THREADS + tid;
                    cp16(sB[nb] + u * 16,
                         (const void*)(cbTq + (size_t)(u >> 5) * C_ + cB + (size_t)(u & 31) * 2));
                }
                CP_COMMIT;
            }

            const int cBase = ch * TN;
            const unsigned long long* Bs =
                (const unsigned long long*)(smem + ((ch & 1) ? OFF_B1 : OFF_B0));

            unsigned long long acc[4][4];
#pragma unroll
            for (int rp = 0; rp < 4; ++rp)
#pragma unroll
                for (int j = 0; j < 4; ++j) acc[rp][j] = 0ull;

            // A rows: floats [8ty..8ty+7] of each k-row (row = 128 floats = 32 ull2)
            // B cols: codes {2tx, 2tx+1, 2tx+32, 2tx+33} (row = 64 ull = 32 ull2)
            const ulonglong2* pA = (const ulonglong2*)As + 2 * ty;
            const ulonglong2* pB = (const ulonglong2*)Bs + tx;
#pragma unroll 8
            for (int k = 0; k < 128; ++k) {
                ulonglong2 a01 = pA[k * 32];
                ulonglong2 a23 = pA[k * 32 + 1];
                ulonglong2 b01 = pB[k * 32];
                ulonglong2 b23 = pB[k * 32 + 16];
                fma2(acc[0][0], a01.x, b01.x); fma2(acc[1][0], a01.y, b01.x);
                fma2(acc[2][0], a23.x, b01.x); fma2(acc[3][0], a23.y, b01.x);
                fma2(acc[0][1], a01.x, b01.y); fma2(acc[1][1], a01.y, b01.y);
                fma2(acc[2][1], a23.x, b01.y); fma2(acc[3][1], a23.y, b01.y);
                fma2(acc[0][2], a01.x, b23.x); fma2(acc[1][2], a01.y, b23.x);
                fma2(acc[2][2], a23.x, b23.x); fma2(acc[3][2], a23.y, b23.x);
                fma2(acc[0][3], a01.x, b23.y); fma2(acc[1][3], a01.y, b23.y);
                fma2(acc[2][3], a23.x, b23.y); fma2(acc[3][3], a23.y, b23.y);
            }

            // scores: c2 - 2*dot, running (val, idx) min with first-min tie-break
            const int cols[4] = {2 * tx, 2 * tx + 1, 2 * tx + 32, 2 * tx + 33};
#pragma unroll
            for (int j = 0; j < 4; ++j) {
                int cg = cBase + cols[j];
                float c2v = c2s[cg];
#pragma unroll
                for (int rp = 0; rp < 4; ++rp) {
                    float lo, hi;
                    unpack2(acc[rp][j], lo, hi);
                    float v0 = fmaf(-2.f, lo, c2v);
                    float v1 = fmaf(-2.f, hi, c2v);
                    int r0 = 2 * rp, r1 = 2 * rp + 1;
                    if (v0 < bestv[r0] || (v0 == bestv[r0] && cg < besti[r0])) { bestv[r0] = v0; besti[r0] = cg; }
                    if (v1 < bestv[r1] || (v1 == bestv[r1] && cg < besti[r1])) { bestv[r1] = v1; besti[r1] = cg; }
                }
            }
        }

        __syncthreads();  // all compute done; B buffers free for rvs/ris/Qs aliases
#pragma unroll
        for (int r = 0; r < 8; ++r) {
            rvs[(8 * ty + r) * 16 + tx] = bestv[r];
            ris[(8 * ty + r) * 16 + tx] = besti[r];
        }
        __syncthreads();
        if (tid < TM) {
            float bv = rvs[tid * 16];
            int bi = ris[tid * 16];
#pragma unroll
            for (int jj = 1; jj < 16; ++jj) {
                float v = rvs[tid * 16 + jj];
                int i2 = ris[tid * 16 + jj];
                if (v < bv || (v == bv && i2 < bi)) { bv = v; bi = i2; }
            }
            bidx[tid] = bi;
        }
        __syncthreads();

        // stage chosen code rows coalesced into Qs (transposed, pad 129)
        {
            int d = tid & 127;
            int r0 = (tid >> 7) * 64;
#pragma unroll 8
            for (int rr = 0; rr < 64; ++rr) {
                int r = r0 + rr;
                Qs[d * 129 + r] = cbq[(size_t)bidx[r] * D_ + d];
            }
        }
        __syncthreads();

        // residual update in smem + loss partial
        {
            int row = tid & 127;
            int dbase = (tid >> 7) * 64;
            float ls = 0.f;
#pragma unroll 8
            for (int dd = 0; dd < 64; ++dd) {
                int d = dbase + dd;
                float nv = As[d * 128 + row] - Qs[d * 129 + row];
                As[d * 128 + row] = nv;
                ls += nv * nv;
            }
            dloss += (double)ls;
        }
        __syncthreads();  // Qs dead before next q's prefetch overwrites B region
    }

    // quantized = x - residual_final, written straight in [B,D,T] layout
    for (int i = 0; i < 64; ++i) {
        int idx = i * THREADS + tid;
        int d = idx >> 7, tc = idx & 127;
        size_t gi = (size_t)d * T_ + tc;
        out[(size_t)b * D_ * T_ + t0 + gi] = xb[gi] - As[d * 128 + tc];
    }

    // loss reduce: warp shuffle -> smem -> one atomicAdd per block
    double v = dloss;
#pragma unroll
    for (int o = 16; o; o >>= 1) v += __shfl_down_sync(0xffffffffu, v, o);
    if ((tid & 31) == 0) lred[tid >> 5] = v;
    __syncthreads();
    if (tid == 0) {
        double tot = 0.0;
#pragma unroll
        for (int w = 0; w < 8; ++w) tot += lred[w];
        atomicAdd(&g_loss, tot);
    }
}

__global__ void k_loss(float* __restrict__ out, int out_size) {
    if (out_size > NOUT) out[NOUT] = (float)(g_loss / (double)((size_t)BT_ * D_));
}

extern "C" void kernel_launch(void* const* d_in, const int* in_sizes, int n_in,
                              void* d_out, int out_size) {
    const float* x = (const float*)d_in[0];
    const float* cb = (const float*)d_in[1];
    float* out = (float*)d_out;

    cudaFuncSetAttribute(k_vq, cudaFuncAttributeMaxDynamicSharedMemorySize, SMEM_BYTES);

    dim3 ptb(32, 8);
    dim3 ptg(C_ / 32, D_ / 32, Q_);
    k_prep<<<ptg, ptb>>>(cb);
    k_c2<<<(Q_ * C_) / 8, 256>>>(cb);
    k_vq<<<BT_ / TM, THREADS, SMEM_BYTES>>>(x, cb, out);
    k_loss<<<1, 1>>>(out, out_size);
}

// round 8
// speedup vs baseline: 2.3093x; 1.3104x over previous
#include <cuda_runtime.h>
#include <cuda_fp16.h>
#include <cstdint>

#define B_ 8
#define D_ 128
#define T_ 4096
#define Q_ 30
#define C_ 1024
#define BT_ (B_ * T_)
#define NOUT (B_ * D_ * T_)

#define TM 128
#define TN 64
#define NCHUNK 16
#define THREADS 256
#define DELTA 0.02f
#define CAP 64

// smem layout (bytes)
#define OFF_AS 0
#define SZ_AS (128 * 128 * 4)        // 65536  residual fp32, [k][row]
#define OFF_A16 (OFF_AS + SZ_AS)     // 65536
#define A16_PLANE 34816              // 128 rows x 272B
#define SZ_A16 (2 * A16_PLANE)       // 69632
#define OFF_BB (OFF_A16 + SZ_A16)    // 135168
#define BB_PLANE 17408               // 64 codes x 272B
#define BB_BUF (2 * BB_PLANE)        // 34816 (2 splits)
#define SZ_BB (2 * BB_BUF)           // 69632 double buffered
#define OFF_C2 (OFF_BB + SZ_BB)      // 204800
#define SZ_C2 (C_ * 4)               // 4096
#define OFF_BI (OFF_C2 + SZ_C2)      // 208896
#define SZ_BI (TM * 4)               // 512
#define OFF_LR (OFF_BI + SZ_BI)      // 209408
#define OFF_CT (OFF_LR + 64)         // 209472 per-row candidate counts (128 ints)
#define OFF_CD (OFF_CT + 512)        // 209984 candidate codes (128 x CAP u16)
#define SMEM_BYTES (OFF_CD + 128 * CAP * 2)  // 226368
// Qs aliases the A16 region (dead between last chunk and next q's convert)
#define OFF_QS OFF_A16               // 128*129*4 = 66048 <= 69632

#define ROWSTRIDE 272

__device__ float g_c2[Q_ * C_];
__device__ double g_loss;
// fp16 2-split codebook: [q][s][code][k]; split1 pre-scaled by 2048
__device__ __align__(16) __half g_bk[(size_t)Q_ * 2 * C_ * D_];

__device__ __forceinline__ void cp16(uint32_t saddr, const void* g) {
    asm volatile("cp.async.cg.shared.global [%0], [%1], 16;\n" ::"r"(saddr), "l"(g));
}
#define CP_COMMIT asm volatile("cp.async.commit_group;\n" ::: "memory")
#define CP_WAIT0 asm volatile("cp.async.wait_group 0;\n" ::: "memory")

__device__ __forceinline__ void ldm4(uint32_t& r0, uint32_t& r1, uint32_t& r2,
                                     uint32_t& r3, uint32_t addr) {
    asm volatile("ldmatrix.sync.aligned.m8n8.x4.shared.b16 {%0,%1,%2,%3}, [%4];"
                 : "=r"(r0), "=r"(r1), "=r"(r2), "=r"(r3)
                 : "r"(addr));
}

__device__ __forceinline__ void mma16816(float& c0, float& c1, float& c2, float& c3,
                                         uint32_t a0, uint32_t a1, uint32_t a2,
                                         uint32_t a3, uint32_t b0, uint32_t b1) {
    asm volatile(
        "mma.sync.aligned.m16n8k16.row.col.f32.f16.f16.f32 "
        "{%0,%1,%2,%3}, {%4,%5,%6,%7}, {%8,%9}, {%0,%1,%2,%3};"
        : "+f"(c0), "+f"(c1), "+f"(c2), "+f"(c3)
        : "r"(a0), "r"(a1), "r"(a2), "r"(a3), "r"(b0), "r"(b1));
}

// ---- prep: split codebook into 2 fp16 planes (low plane scaled by 2048) ----
__global__ void k_prep(const float* __restrict__ cb) {
    int qc = blockIdx.x;  // q*1024 + code
    int k = threadIdx.x;  // 0..127
    float a = cb[(size_t)qc * D_ + k];
    __half h0 = __float2half_rn(a);
    __half h1 = __float2half_rn((a - __half2float(h0)) * 2048.0f);
    int q = qc >> 10, code = qc & 1023;
    g_bk[(((size_t)q * 2 + 0) * C_ + code) * D_ + k] = h0;
    g_bk[(((size_t)q * 2 + 1) * C_ + code) * D_ + k] = h1;
}

// per-code squared norms + zero loss accumulator
__global__ void k_c2(const float* __restrict__ cb) {
    int code = blockIdx.x * 8 + (threadIdx.x >> 5);
    int lane = threadIdx.x & 31;
    float4 v = *(const float4*)(cb + (size_t)code * D_ + lane * 4);
    float s = v.x * v.x + v.y * v.y + v.z * v.z + v.w * v.w;
#pragma unroll
    for (int o = 16; o; o >>= 1) s += __shfl_down_sync(0xffffffffu, s, o);
    if (lane == 0) g_c2[code] = s;
    if (blockIdx.x == 0 && threadIdx.x == 0) g_loss = 0.0;
}

// ---- fused VQ: fp16 split mma.sync screening + exact fp32 candidate rescore ----
__global__ __launch_bounds__(THREADS, 1) void k_vq(const float* __restrict__ x,
                                                   const float* __restrict__ cb_all,
                                                   float* __restrict__ out) {
    extern __shared__ char smem[];
    float* As = (float*)(smem + OFF_AS);
    float* Qs = (float*)(smem + OFF_QS);
    float* c2s = (float*)(smem + OFF_C2);
    int* bidx = (int*)(smem + OFF_BI);
    double* lred = (double*)(smem + OFF_LR);
    int* ccnt = (int*)(smem + OFF_CT);
    unsigned short* cand = (unsigned short*)(smem + OFF_CD);

    const int tid = threadIdx.x;
    const int lane = tid & 31;
    const int w = tid >> 5;  // 0..7
    const int bt0 = blockIdx.x * TM;
    const int b = bt0 / T_;
    const int t0 = bt0 % T_;
    const float* xb = x + (size_t)b * D_ * T_ + t0;

    const uint32_t sBase = (uint32_t)__cvta_generic_to_shared(smem);
    const uint32_t sA16 = sBase + OFF_A16;
    const uint32_t sBB = sBase + OFF_BB;

    const int arow = 16 * w + (lane & 15);
    const uint32_t aoff = (uint32_t)(arow * ROWSTRIDE + ((lane >= 16) ? 16 : 0));
    const int brow = (lane & 7) + ((lane >= 16) ? 8 : 0);
    const uint32_t boff = (uint32_t)(brow * ROWSTRIDE + ((lane & 8) ? 16 : 0));

    // rows owned by this thread's D fragments
    const int R0 = 16 * w + (lane >> 2);
    const int R1 = R0 + 8;

    // load residual tile As[k*128+row]
    for (int i = 0; i < 64; ++i) {
        int idx = i * THREADS + tid;
        int d = idx >> 7, tc = idx & 127;
        As[d * 128 + tc] = xb[(size_t)d * T_ + tc];
    }
    __syncthreads();

    double dloss = 0.0;

    for (int q = 0; q < Q_; ++q) {
        const float* cbq = cb_all + (size_t)q * C_ * D_;
        for (int i = tid; i < C_; i += THREADS) c2s[i] = g_c2[q * C_ + i];
        if (tid < TM) ccnt[tid] = 0;

        // ---- convert residual fp32 -> 2 fp16 planes (low scaled by 2048) ----
        {
            int s = tid >> 7;
            int row = tid & 127;
            uint32_t* dst = (uint32_t*)(smem + OFF_A16 + s * A16_PLANE + row * ROWSTRIDE);
#pragma unroll 8
            for (int k = 0; k < 128; k += 2) {
                float a0 = As[k * 128 + row];
                float a1 = As[(k + 1) * 128 + row];
                __half u0, u1;
                if (s == 0) {
                    u0 = __float2half_rn(a0);
                    u1 = __float2half_rn(a1);
                } else {
                    u0 = __float2half_rn((a0 - __half2float(__float2half_rn(a0))) * 2048.0f);
                    u1 = __float2half_rn((a1 - __half2float(__float2half_rn(a1))) * 2048.0f);
                }
                dst[k >> 1] = (uint32_t)__half_as_ushort(u0) |
                              ((uint32_t)__half_as_ushort(u1) << 16);
            }
        }
        __syncthreads();  // A16/c2s/ccnt ready

        // prefetch chunk 0
        {
            const __half* src0 = g_bk + ((size_t)q * 2 * C_) * D_;
#pragma unroll
            for (int it = 0; it < 8; ++it) {
                int u = it * THREADS + tid;
                int s = u >> 10, code = (u >> 4) & 63, blk = u & 15;
                cp16(sBB + s * BB_PLANE + code * ROWSTRIDE + blk * 16,
                     src0 + ((size_t)s * C_ + code) * D_ + blk * 8);
            }
            CP_COMMIT;
        }

        const float INF = __int_as_float(0x7f800000);
        float rm0 = INF, rm1 = INF;  // running fast min per owned row

        for (int ch = 0; ch < NCHUNK; ++ch) {
            CP_WAIT0;
            __syncthreads();

            if (ch + 1 < NCHUNK) {
                const __half* srcn = g_bk + ((size_t)q * 2 * C_ + (ch + 1) * TN) * D_;
                uint32_t dstb = sBB + ((ch + 1) & 1) * BB_BUF;
#pragma unroll
                for (int it = 0; it < 8; ++it) {
                    int u = it * THREADS + tid;
                    int s = u >> 10, code = (u >> 4) & 63, blk = u & 15;
                    cp16(dstb + s * BB_PLANE + code * ROWSTRIDE + blk * 16,
                         srcn + ((size_t)s * C_ + code) * D_ + blk * 8);
                }
                CP_COMMIT;
            }

            const uint32_t bufB = sBB + (ch & 1) * BB_BUF;

            float chi[8][4], clo[8][4];
#pragma unroll
            for (int nt = 0; nt < 8; ++nt)
#pragma unroll
                for (int j = 0; j < 4; ++j) { chi[nt][j] = 0.f; clo[nt][j] = 0.f; }

#pragma unroll
            for (int kk = 0; kk < 8; ++kk) {
                uint32_t a0[4], a1[4];
                ldm4(a0[0], a0[1], a0[2], a0[3], sA16 + aoff + kk * 32);
                ldm4(a1[0], a1[1], a1[2], a1[3], sA16 + A16_PLANE + aoff + kk * 32);
#pragma unroll
                for (int ntp = 0; ntp < 4; ++ntp) {
                    uint32_t b0[4], b1[4];
                    uint32_t bbase = bufB + boff + ntp * 16 * ROWSTRIDE + kk * 32;
                    ldm4(b0[0], b0[1], b0[2], b0[3], bbase);
                    ldm4(b1[0], b1[1], b1[2], b1[3], bbase + BB_PLANE);
                    float* hl = chi[2 * ntp];
                    float* hh = chi[2 * ntp + 1];
                    float* ll = clo[2 * ntp];
                    float* lh = clo[2 * ntp + 1];
                    mma16816(hl[0], hl[1], hl[2], hl[3], a0[0], a0[1], a0[2], a0[3], b0[0], b0[1]);
                    mma16816(hh[0], hh[1], hh[2], hh[3], a0[0], a0[1], a0[2], a0[3], b0[2], b0[3]);
                    mma16816(ll[0], ll[1], ll[2], ll[3], a0[0], a0[1], a0[2], a0[3], b1[0], b1[1]);
                    mma16816(ll[0], ll[1], ll[2], ll[3], a1[0], a1[1], a1[2], a1[3], b0[0], b0[1]);
                    mma16816(lh[0], lh[1], lh[2], lh[3], a0[0], a0[1], a0[2], a0[3], b1[2], b1[3]);
                    mma16816(lh[0], lh[1], lh[2], lh[3], a1[0], a1[1], a1[2], a1[3], b0[2], b0[3]);
                }
            }

            // fast scores; rows R0 (j=0,1), R1 (j=2,3); cols cg, cg+1
            float sc[8][4];
            float cm0 = INF, cm1 = INF;
#pragma unroll
            for (int nt = 0; nt < 8; ++nt) {
                int cg = ch * TN + nt * 8 + 2 * (lane & 3);
                float c2a = c2s[cg], c2b = c2s[cg + 1];
                float s0 = fmaf(-2.f, chi[nt][0], c2a);
                s0 = fmaf(-9.765625e-4f, clo[nt][0], s0);
                float s1 = fmaf(-2.f, chi[nt][1], c2b);
                s1 = fmaf(-9.765625e-4f, clo[nt][1], s1);
                float s2 = fmaf(-2.f, chi[nt][2], c2a);
                s2 = fmaf(-9.765625e-4f, clo[nt][2], s2);
                float s3 = fmaf(-2.f, chi[nt][3], c2b);
                s3 = fmaf(-9.765625e-4f, clo[nt][3], s3);
                sc[nt][0] = s0; sc[nt][1] = s1; sc[nt][2] = s2; sc[nt][3] = s3;
                cm0 = fminf(cm0, fminf(s0, s1));
                cm1 = fminf(cm1, fminf(s2, s3));
            }
            // chunk min across the 4 lanes of the quad
#pragma unroll
            for (int m = 1; m <= 2; m <<= 1) {
                cm0 = fminf(cm0, __shfl_xor_sync(0xffffffffu, cm0, m));
                cm1 = fminf(cm1, __shfl_xor_sync(0xffffffffu, cm1, m));
            }
            rm0 = fminf(rm0, cm0);
            rm1 = fminf(rm1, cm1);
            float th0 = rm0 + DELTA, th1 = rm1 + DELTA;

            // append candidates
#pragma unroll
            for (int nt = 0; nt < 8; ++nt) {
                int cg = ch * TN + nt * 8 + 2 * (lane & 3);
                if (sc[nt][0] < th0) { int p = atomicAdd(&ccnt[R0], 1); if (p < CAP) cand[R0 * CAP + p] = (unsigned short)cg; }
                if (sc[nt][1] < th0) { int p = atomicAdd(&ccnt[R0], 1); if (p < CAP) cand[R0 * CAP + p] = (unsigned short)(cg + 1); }
                if (sc[nt][2] < th1) { int p = atomicAdd(&ccnt[R1], 1); if (p < CAP) cand[R1 * CAP + p] = (unsigned short)cg; }
                if (sc[nt][3] < th1) { int p = atomicAdd(&ccnt[R1], 1); if (p < CAP) cand[R1 * CAP + p] = (unsigned short)(cg + 1); }
            }
        }
        __syncthreads();  // candidates visible

        // ---- exact fp32 rescore of candidates; lexicographic (val, idx) min ----
#pragma unroll
        for (int rr = 0; rr < 2; ++rr) {
            int r = rr ? R1 : R0;
            int n = ccnt[r];
            bool ovf = n > CAP;
            if (ovf) n = C_;  // full scan fallback
            else if (n > CAP) n = CAP;
            float bv = INF;
            int bi = 0x7fffffff;
            for (int i = lane & 3; i < n; i += 4) {
                int code = ovf ? i : (int)cand[r * CAP + i];
                const float* cp = cbq + (size_t)code * D_;
                float s = 0.f;
#pragma unroll 8
                for (int d = 0; d < 128; ++d) s = fmaf(As[d * 128 + r], cp[d], s);
                float scv = fmaf(-2.f, s, c2s[code]);
                if (scv < bv || (scv == bv && code < bi)) { bv = scv; bi = code; }
            }
#pragma unroll
            for (int m = 1; m <= 2; m <<= 1) {
                float ov = __shfl_xor_sync(0xffffffffu, bv, m);
                int oi = __shfl_xor_sync(0xffffffffu, bi, m);
                if (ov < bv || (ov == bv && oi < bi)) { bv = ov; bi = oi; }
            }
            if ((lane & 3) == 0) bidx[r] = bi;
        }
        __syncthreads();  // bidx ready; A16 reads done (Qs aliases A16)

        // gather chosen code rows into Qs (transposed, pad 129)
        {
            int d = tid & 127;
            int r0 = (tid >> 7) * 64;
#pragma unroll 8
            for (int rr = 0; rr < 64; ++rr) {
                int r = r0 + rr;
                Qs[d * 129 + r] = cbq[(size_t)bidx[r] * D_ + d];
            }
        }
        __syncthreads();

        // residual update + loss partial
        {
            int row = tid & 127;
            int dbase = (tid >> 7) * 64;
            float ls = 0.f;
#pragma unroll 8
            for (int dd = 0; dd < 64; ++dd) {
                int d = dbase + dd;
                float nv = As[d * 128 + row] - Qs[d * 129 + row];
                As[d * 128 + row] = nv;
                ls += nv * nv;
            }
            dloss += (double)ls;
        }
        __syncthreads();
    }

    // quantized = x - residual_final, straight [B,D,T]
    for (int i = 0; i < 64; ++i) {
        int idx = i * THREADS + tid;
        int d = idx >> 7, tc = idx & 127;
        size_t gi = (size_t)d * T_ + tc;
        out[(size_t)b * D_ * T_ + t0 + gi] = xb[gi] - As[d * 128 + tc];
    }

    // loss reduce
    double v = dloss;
#pragma unroll
    for (int o = 16; o; o >>= 1) v += __shfl_down_sync(0xffffffffu, v, o);
    if (lane == 0) lred[w] = v;
    __syncthreads();
    if (tid == 0) {
        double tot = 0.0;
#pragma unroll
        for (int i = 0; i < 8; ++i) tot += lred[i];
        atomicAdd(&g_loss, tot);
    }
}

__global__ void k_loss(float* __restrict__ out, int out_size) {
    if (out_size > NOUT) out[NOUT] = (float)(g_loss / (double)((size_t)BT_ * D_));
}

extern "C" void kernel_launch(void* const* d_in, const int* in_sizes, int n_in,
                              void* d_out, int out_size) {
    const float* x = (const float*)d_in[0];
    const float* cb = (const float*)d_in[1];
    float* out = (float*)d_out;

    cudaFuncSetAttribute(k_vq, cudaFuncAttributeMaxDynamicSharedMemorySize, SMEM_BYTES);

    k_prep<<<Q_ * C_, 128>>>(cb);
    k_c2<<<(Q_ * C_) / 8, 256>>>(cb);
    k_vq<<<BT_ / TM, THREADS, SMEM_BYTES>>>(x, cb, out);
    k_loss<<<1, 1>>>(out, out_size);
}

// round 9
// speedup vs baseline: 4.5569x; 1.9733x over previous
#include <cuda_runtime.h>
#include <cuda_fp16.h>
#include <cstdint>

#define B_ 8
#define D_ 128
#define T_ 4096
#define Q_ 30
#define C_ 1024
#define BT_ (B_ * T_)
#define NOUT (B_ * D_ * T_)

#define TM 128
#define TN 128
#define NCHUNK 8
#define THREADS 256
#define DELTA 0.75f
#define CAP 32

// smem layout (bytes)
#define OFF_AS 0
#define SZ_AS (128 * 128 * 4)        // 65536  residual fp32, [k][row]
#define OFF_A16 (OFF_AS + SZ_AS)     // 65536
#define A16_PLANE 34816              // 128 rows x 272B (fp16 high plane only)
#define OFF_BB (OFF_A16 + A16_PLANE) // 100352
#define BB_BUF 34816                 // 128 codes x 272B, single plane
#define SZ_BB (2 * BB_BUF)           // 69632 double buffered
#define OFF_C2 (OFF_BB + SZ_BB)      // 169984
#define SZ_C2 (C_ * 4)               // 4096
#define OFF_BI (OFF_C2 + SZ_C2)      // 174080
#define SZ_BI (TM * 4)               // 512
#define OFF_LR (OFF_BI + SZ_BI)      // 174592
#define OFF_CT (OFF_LR + 64)         // 174656 per-row candidate counts
#define OFF_CD (OFF_CT + 512)        // 175168 candidate codes (128 x CAP u16)
#define SMEM_BYTES (OFF_CD + 128 * CAP * 2)  // 183360
// Qs aliases the BB region (dead after last chunk's ldmatrix reads)
#define OFF_QS OFF_BB                // 128*129*4 = 66048 <= 69632

#define ROWSTRIDE 272

__device__ float g_c2[Q_ * C_];
__device__ double g_loss;
// fp16 high-plane codebook: [q][code][k]
__device__ __align__(16) __half g_bk[(size_t)Q_ * C_ * D_];

__device__ __forceinline__ void cp16(uint32_t saddr, const void* g) {
    asm volatile("cp.async.cg.shared.global [%0], [%1], 16;\n" ::"r"(saddr), "l"(g));
}
#define CP_COMMIT asm volatile("cp.async.commit_group;\n" ::: "memory")
#define CP_WAIT0 asm volatile("cp.async.wait_group 0;\n" ::: "memory")

__device__ __forceinline__ void ldm4(uint32_t& r0, uint32_t& r1, uint32_t& r2,
                                     uint32_t& r3, uint32_t addr) {
    asm volatile("ldmatrix.sync.aligned.m8n8.x4.shared.b16 {%0,%1,%2,%3}, [%4];"
                 : "=r"(r0), "=r"(r1), "=r"(r2), "=r"(r3)
                 : "r"(addr));
}

__device__ __forceinline__ void mma16816(float& c0, float& c1, float& c2, float& c3,
                                         uint32_t a0, uint32_t a1, uint32_t a2,
                                         uint32_t a3, uint32_t b0, uint32_t b1) {
    asm volatile(
        "mma.sync.aligned.m16n8k16.row.col.f32.f16.f16.f32 "
        "{%0,%1,%2,%3}, {%4,%5,%6,%7}, {%8,%9}, {%0,%1,%2,%3};"
        : "+f"(c0), "+f"(c1), "+f"(c2), "+f"(c3)
        : "r"(a0), "r"(a1), "r"(a2), "r"(a3), "r"(b0), "r"(b1));
}

// ---- prep: fp16 high plane of codebook ----
__global__ void k_prep(const float* __restrict__ cb) {
    int qc = blockIdx.x;  // q*1024 + code
    int k = threadIdx.x;  // 0..127
    float a = cb[(size_t)qc * D_ + k];
    g_bk[(size_t)qc * D_ + k] = __float2half_rn(a);
}

// per-code squared norms + zero loss accumulator
__global__ void k_c2(const float* __restrict__ cb) {
    int code = blockIdx.x * 8 + (threadIdx.x >> 5);
    int lane = threadIdx.x & 31;
    float4 v = *(const float4*)(cb + (size_t)code * D_ + lane * 4);
    float s = v.x * v.x + v.y * v.y + v.z * v.z + v.w * v.w;
#pragma unroll
    for (int o = 16; o; o >>= 1) s += __shfl_down_sync(0xffffffffu, s, o);
    if (lane == 0) g_c2[code] = s;
    if (blockIdx.x == 0 && threadIdx.x == 0) g_loss = 0.0;
}

// ---- fused VQ: fp16 mma.sync screening + exact fp32 candidate rescore ----
__global__ __launch_bounds__(THREADS, 1) void k_vq(const float* __restrict__ x,
                                                   const float* __restrict__ cb_all,
                                                   float* __restrict__ out) {
    extern __shared__ char smem[];
    float* As = (float*)(smem + OFF_AS);
    float* Qs = (float*)(smem + OFF_QS);
    float* c2s = (float*)(smem + OFF_C2);
    int* bidx = (int*)(smem + OFF_BI);
    double* lred = (double*)(smem + OFF_LR);
    int* ccnt = (int*)(smem + OFF_CT);
    unsigned short* cand = (unsigned short*)(smem + OFF_CD);

    const int tid = threadIdx.x;
    const int lane = tid & 31;
    const int w = tid >> 5;  // 0..7
    const int bt0 = blockIdx.x * TM;
    const int b = bt0 / T_;
    const int t0 = bt0 % T_;
    const float* xb = x + (size_t)b * D_ * T_ + t0;

    const uint32_t sBase = (uint32_t)__cvta_generic_to_shared(smem);
    const uint32_t sA16 = sBase + OFF_A16;
    const uint32_t sBB = sBase + OFF_BB;

    const int arow = 16 * w + (lane & 15);
    const uint32_t aoff = (uint32_t)(arow * ROWSTRIDE + ((lane >= 16) ? 16 : 0));
    const int brow = (lane & 7) + ((lane >= 16) ? 8 : 0);
    const uint32_t boff = (uint32_t)(brow * ROWSTRIDE + ((lane & 8) ? 16 : 0));

    // rows owned by this thread's D fragments
    const int R0 = 16 * w + (lane >> 2);
    const int R1 = R0 + 8;

    // load residual tile As[k*128+row]
    for (int i = 0; i < 64; ++i) {
        int idx = i * THREADS + tid;
        int d = idx >> 7, tc = idx & 127;
        As[d * 128 + tc] = xb[(size_t)d * T_ + tc];
    }
    __syncthreads();

    double dloss = 0.0;

    for (int q = 0; q < Q_; ++q) {
        const float* cbq = cb_all + (size_t)q * C_ * D_;
        for (int i = tid; i < C_; i += THREADS) c2s[i] = g_c2[q * C_ + i];
        if (tid < TM) ccnt[tid] = 0;

        // ---- convert residual fp32 -> fp16 high plane (ldmatrix layout) ----
        {
            int row = tid & 127;
            int kh = tid >> 7;   // half of k-range per thread
            uint32_t* dst = (uint32_t*)(smem + OFF_A16 + row * ROWSTRIDE);
#pragma unroll 8
            for (int k = kh * 64; k < kh * 64 + 64; k += 2) {
                float a0 = As[k * 128 + row];
                float a1 = As[(k + 1) * 128 + row];
                dst[k >> 1] = (uint32_t)__half_as_ushort(__float2half_rn(a0)) |
                              ((uint32_t)__half_as_ushort(__float2half_rn(a1)) << 16);
            }
        }
        __syncthreads();  // A16/c2s/ccnt ready

        // prefetch chunk 0 (128 codes x 256B = 2048 x 16B units)
        {
            const __half* src0 = g_bk + (size_t)q * C_ * D_;
#pragma unroll
            for (int it = 0; it < 8; ++it) {
                int u = it * THREADS + tid;
                int code = u >> 4, blk = u & 15;
                cp16(sBB + code * ROWSTRIDE + blk * 16,
                     src0 + (size_t)code * D_ + blk * 8);
            }
            CP_COMMIT;
        }

        const float INF = __int_as_float(0x7f800000);
        float rm0 = INF, rm1 = INF;

        for (int ch = 0; ch < NCHUNK; ++ch) {
            CP_WAIT0;
            __syncthreads();

            if (ch + 1 < NCHUNK) {
                const __half* srcn = g_bk + ((size_t)q * C_ + (ch + 1) * TN) * D_;
                uint32_t dstb = sBB + ((ch + 1) & 1) * BB_BUF;
#pragma unroll
                for (int it = 0; it < 8; ++it) {
                    int u = it * THREADS + tid;
                    int code = u >> 4, blk = u & 15;
                    cp16(dstb + code * ROWSTRIDE + blk * 16,
                         srcn + (size_t)code * D_ + blk * 8);
                }
                CP_COMMIT;
            }

            const uint32_t bufB = sBB + (ch & 1) * BB_BUF;

            float c[16][4];
#pragma unroll
            for (int nt = 0; nt < 16; ++nt)
#pragma unroll
                for (int j = 0; j < 4; ++j) c[nt][j] = 0.f;

#pragma unroll
            for (int kk = 0; kk < 8; ++kk) {
                uint32_t a0[4];
                ldm4(a0[0], a0[1], a0[2], a0[3], sA16 + aoff + kk * 32);
#pragma unroll
                for (int ntp = 0; ntp < 8; ++ntp) {
                    uint32_t b0[4];
                    uint32_t bbase = bufB + boff + ntp * 16 * ROWSTRIDE + kk * 32;
                    ldm4(b0[0], b0[1], b0[2], b0[3], bbase);
                    float* cl = c[2 * ntp];
                    float* ch2 = c[2 * ntp + 1];
                    mma16816(cl[0], cl[1], cl[2], cl[3], a0[0], a0[1], a0[2], a0[3], b0[0], b0[1]);
                    mma16816(ch2[0], ch2[1], ch2[2], ch2[3], a0[0], a0[1], a0[2], a0[3], b0[2], b0[3]);
                }
            }

            // fast scores; rows R0 (j=0,1), R1 (j=2,3); cols cg, cg+1
            float sc[16][4];
            float cm0 = INF, cm1 = INF;
#pragma unroll
            for (int nt = 0; nt < 16; ++nt) {
                int cg = ch * TN + nt * 8 + 2 * (lane & 3);
                float c2a = c2s[cg], c2b = c2s[cg + 1];
                float s0 = fmaf(-2.f, c[nt][0], c2a);
                float s1 = fmaf(-2.f, c[nt][1], c2b);
                float s2 = fmaf(-2.f, c[nt][2], c2a);
                float s3 = fmaf(-2.f, c[nt][3], c2b);
                sc[nt][0] = s0; sc[nt][1] = s1; sc[nt][2] = s2; sc[nt][3] = s3;
                cm0 = fminf(cm0, fminf(s0, s1));
                cm1 = fminf(cm1, fminf(s2, s3));
            }
#pragma unroll
            for (int m = 1; m <= 2; m <<= 1) {
                cm0 = fminf(cm0, __shfl_xor_sync(0xffffffffu, cm0, m));
                cm1 = fminf(cm1, __shfl_xor_sync(0xffffffffu, cm1, m));
            }
            rm0 = fminf(rm0, cm0);
            rm1 = fminf(rm1, cm1);
            float th0 = rm0 + DELTA, th1 = rm1 + DELTA;

            // append candidates
#pragma unroll
            for (int nt = 0; nt < 16; ++nt) {
                int cg = ch * TN + nt * 8 + 2 * (lane & 3);
                if (sc[nt][0] < th0) { int p = atomicAdd(&ccnt[R0], 1); if (p < CAP) cand[R0 * CAP + p] = (unsigned short)cg; }
                if (sc[nt][1] < th0) { int p = atomicAdd(&ccnt[R0], 1); if (p < CAP) cand[R0 * CAP + p] = (unsigned short)(cg + 1); }
                if (sc[nt][2] < th1) { int p = atomicAdd(&ccnt[R1], 1); if (p < CAP) cand[R1 * CAP + p] = (unsigned short)cg; }
                if (sc[nt][3] < th1) { int p = atomicAdd(&ccnt[R1], 1); if (p < CAP) cand[R1 * CAP + p] = (unsigned short)(cg + 1); }
            }
        }
        __syncthreads();  // candidates visible; BB reads done (Qs aliases BB)

        // ---- exact fp32 rescore of candidates; lexicographic (val, idx) min ----
#pragma unroll
        for (int rr = 0; rr < 2; ++rr) {
            int r = rr ? R1 : R0;
            int n = ccnt[r];
            bool ovf = n > CAP;
            if (ovf) n = C_;  // full scan fallback (guaranteed-correct path)
            float bv = INF;
            int bi = 0x7fffffff;
            for (int i = lane & 3; i < n; i += 4) {
                int code = ovf ? i : (int)cand[r * CAP + i];
                const float4* cp4 = (const float4*)(cbq + (size_t)code * D_);
                float s = 0.f;
#pragma unroll 8
                for (int dq = 0; dq < 32; ++dq) {
                    float4 cv = cp4[dq];
                    s = fmaf(As[(4 * dq + 0) * 128 + r], cv.x, s);
                    s = fmaf(As[(4 * dq + 1) * 128 + r], cv.y, s);
                    s = fmaf(As[(4 * dq + 2) * 128 + r], cv.z, s);
                    s = fmaf(As[(4 * dq + 3) * 128 + r], cv.w, s);
                }
                float scv = fmaf(-2.f, s, c2s[code]);
                if (scv < bv || (scv == bv && code < bi)) { bv = scv; bi = code; }
            }
#pragma unroll
            for (int m = 1; m <= 2; m <<= 1) {
                float ov = __shfl_xor_sync(0xffffffffu, bv, m);
                int oi = __shfl_xor_sync(0xffffffffu, bi, m);
                if (ov < bv || (ov == bv && oi < bi)) { bv = ov; bi = oi; }
            }
            if ((lane & 3) == 0) bidx[r] = bi;
        }
        __syncthreads();

        // gather chosen code rows into Qs (transposed, pad 129)
        {
            int d = tid & 127;
            int r0 = (tid >> 7) * 64;
#pragma unroll 8
            for (int rr = 0; rr < 64; ++rr) {
                int r = r0 + rr;
                Qs[d * 129 + r] = cbq[(size_t)bidx[r] * D_ + d];
            }
        }
        __syncthreads();

        // residual update + loss partial
        {
            int row = tid & 127;
            int dbase = (tid >> 7) * 64;
            float ls = 0.f;
#pragma unroll 8
            for (int dd = 0; dd < 64; ++dd) {
                int d = dbase + dd;
                float nv = As[d * 128 + row] - Qs[d * 129 + row];
                As[d * 128 + row] = nv;
                ls += nv * nv;
            }
            dloss += (double)ls;
        }
        __syncthreads();  // As settled before next q convert; Qs dead before BB reuse
    }

    // quantized = x - residual_final, straight [B,D,T]
    for (int i = 0; i < 64; ++i) {
        int idx = i * THREADS + tid;
        int d = idx >> 7, tc = idx & 127;
        size_t gi = (size_t)d * T_ + tc;
        out[(size_t)b * D_ * T_ + t0 + gi] = xb[gi] - As[d * 128 + tc];
    }

    // loss reduce
    double v = dloss;
#pragma unroll
    for (int o = 16; o; o >>= 1) v += __shfl_down_sync(0xffffffffu, v, o);
    if (lane == 0) lred[w] = v;
    __syncthreads();
    if (tid == 0) {
        double tot = 0.0;
#pragma unroll
        for (int i = 0; i < 8; ++i) tot += lred[i];
        atomicAdd(&g_loss, tot);
    }
}

__global__ void k_loss(float* __restrict__ out, int out_size) {
    if (out_size > NOUT) out[NOUT] = (float)(g_loss / (double)((size_t)BT_ * D_));
}

extern "C" void kernel_launch(void* const* d_in, const int* in_sizes, int n_in,
                              void* d_out, int out_size) {
    const float* x = (const float*)d_in[0];
    const float* cb = (const float*)d_in[1];
    float* out = (float*)d_out;

    cudaFuncSetAttribute(k_vq, cudaFuncAttributeMaxDynamicSharedMemorySize, SMEM_BYTES);

    k_prep<<<Q_ * C_, 128>>>(cb);
    k_c2<<<(Q_ * C_) / 8, 256>>>(cb);
    k_vq<<<BT_ / TM, THREADS, SMEM_BYTES>>>(x, cb, out);
    k_loss<<<1, 1>>>(out, out_size);
}

// round 10
// speedup vs baseline: 5.1470x; 1.1295x over previous
#include <cuda_runtime.h>
#include <cuda_fp16.h>
#include <cstdint>

#define B_ 8
#define D_ 128
#define T_ 4096
#define Q_ 30
#define C_ 1024
#define BT_ (B_ * T_)
#define NOUT (B_ * D_ * T_)

#define TM 128
#define TN 128
#define NCHUNK 8
#define THREADS 512
#define DELTA 0.75f
#define CAP 32

// smem layout (bytes)
#define OFF_AS 0
#define SZ_AS (128 * 128 * 4)        // 65536  residual fp32, [k][row]
#define OFF_A16 (OFF_AS + SZ_AS)     // 65536
#define A16_PLANE 34816              // 128 rows x 272B fp16
#define OFF_BB (OFF_A16 + A16_PLANE) // 100352
#define BB_BUF 34816                 // 128 codes x 272B
#define SZ_BB (2 * BB_BUF)           // 69632 double buffered
#define OFF_C2 (OFF_BB + SZ_BB)      // 169984
#define SZ_C2 (C_ * 4)               // 4096
#define OFF_BI (OFF_C2 + SZ_C2)      // 174080
#define SZ_BI (TM * 4)               // 512
#define OFF_LR (OFF_BI + SZ_BI)      // 174592 (16 doubles)
#define OFF_CT (OFF_LR + 128)        // 174720 per-row candidate counts
#define OFF_CD (OFF_CT + 512)        // 175232 candidate codes (128 x CAP u16)
#define SMEM_BYTES (OFF_CD + 128 * CAP * 2)  // 183424

#define ROWSTRIDE 272

__device__ float g_c2[Q_ * C_];
__device__ double g_loss;
// fp16 high-plane codebook: [q][code][k]
__device__ __align__(16) __half g_bk[(size_t)Q_ * C_ * D_];

__device__ __forceinline__ void cp16(uint32_t saddr, const void* g) {
    asm volatile("cp.async.cg.shared.global [%0], [%1], 16;\n" ::"r"(saddr), "l"(g));
}
#define CP_COMMIT asm volatile("cp.async.commit_group;\n" ::: "memory")
#define CP_WAIT0 asm volatile("cp.async.wait_group 0;\n" ::: "memory")

__device__ __forceinline__ void ldm4(uint32_t& r0, uint32_t& r1, uint32_t& r2,
                                     uint32_t& r3, uint32_t addr) {
    asm volatile("ldmatrix.sync.aligned.m8n8.x4.shared.b16 {%0,%1,%2,%3}, [%4];"
                 : "=r"(r0), "=r"(r1), "=r"(r2), "=r"(r3)
                 : "r"(addr));
}

__device__ __forceinline__ void mma16816(float& c0, float& c1, float& c2, float& c3,
                                         uint32_t a0, uint32_t a1, uint32_t a2,
                                         uint32_t a3, uint32_t b0, uint32_t b1) {
    asm volatile(
        "mma.sync.aligned.m16n8k16.row.col.f32.f16.f16.f32 "
        "{%0,%1,%2,%3}, {%4,%5,%6,%7}, {%8,%9}, {%0,%1,%2,%3};"
        : "+f"(c0), "+f"(c1), "+f"(c2), "+f"(c3)
        : "r"(a0), "r"(a1), "r"(a2), "r"(a3), "r"(b0), "r"(b1));
}

// ---- prep: fp16 high plane of codebook ----
__global__ void k_prep(const float* __restrict__ cb) {
    int qc = blockIdx.x;
    int k = threadIdx.x;
    g_bk[(size_t)qc * D_ + k] = __float2half_rn(cb[(size_t)qc * D_ + k]);
}

// per-code squared norms + zero loss accumulator
__global__ void k_c2(const float* __restrict__ cb) {
    int code = blockIdx.x * 8 + (threadIdx.x >> 5);
    int lane = threadIdx.x & 31;
    float4 v = *(const float4*)(cb + (size_t)code * D_ + lane * 4);
    float s = v.x * v.x + v.y * v.y + v.z * v.z + v.w * v.w;
#pragma unroll
    for (int o = 16; o; o >>= 1) s += __shfl_down_sync(0xffffffffu, s, o);
    if (lane == 0) g_c2[code] = s;
    if (blockIdx.x == 0 && threadIdx.x == 0) g_loss = 0.0;
}

// ---- fused VQ: fp16 mma.sync screening + exact fp32 candidate rescore ----
__global__ __launch_bounds__(THREADS, 1) void k_vq(const float* __restrict__ x,
                                                   const float* __restrict__ cb_all,
                                                   float* __restrict__ out) {
    extern __shared__ char smem[];
    float* As = (float*)(smem + OFF_AS);
    float* c2s = (float*)(smem + OFF_C2);
    int* bidx = (int*)(smem + OFF_BI);
    double* lred = (double*)(smem + OFF_LR);
    int* ccnt = (int*)(smem + OFF_CT);
    unsigned short* cand = (unsigned short*)(smem + OFF_CD);

    const int tid = threadIdx.x;
    const int lane = tid & 31;
    const int w = tid >> 5;        // 0..15
    const int wr = w & 7;          // row-warp 0..7
    const int whalf = w >> 3;      // code half 0/1
    const int bt0 = blockIdx.x * TM;
    const int b = bt0 / T_;
    const int t0 = bt0 % T_;
    const float* xb = x + (size_t)b * D_ * T_ + t0;

    const uint32_t sBase = (uint32_t)__cvta_generic_to_shared(smem);
    const uint32_t sA16 = sBase + OFF_A16;
    const uint32_t sBB = sBase + OFF_BB;

    const int arow = 16 * wr + (lane & 15);
    const uint32_t aoff = (uint32_t)(arow * ROWSTRIDE + ((lane >= 16) ? 16 : 0));
    const int brow = (lane & 7) + ((lane >= 16) ? 8 : 0);
    const uint32_t boff =
        (uint32_t)(whalf * 64 * ROWSTRIDE + brow * ROWSTRIDE + ((lane & 8) ? 16 : 0));

    // rows owned by this warp's D fragments
    const int R0 = 16 * wr + (lane >> 2);
    const int R1 = R0 + 8;

    // fused-update mapping: 512 thr = (row, quarter)
    const int urow = tid & 127;
    const int uq = tid >> 7;       // 0..3 -> 32 d's each
    const int udbase = uq * 32;

    // load residual tile As[k*128+row]
    for (int i = 0; i < 32; ++i) {
        int idx = i * THREADS + tid;
        int d = idx >> 7, tc = idx & 127;
        As[d * 128 + tc] = xb[(size_t)d * T_ + tc];
    }
    __syncthreads();

    // initial fp16 convert (A16 plane for q=0)
    {
        uint32_t* dst = (uint32_t*)(smem + OFF_A16 + urow * ROWSTRIDE);
#pragma unroll 8
        for (int k = udbase; k < udbase + 32; k += 2) {
            float a0 = As[k * 128 + urow];
            float a1 = As[(k + 1) * 128 + urow];
            dst[k >> 1] = (uint32_t)__half_as_ushort(__float2half_rn(a0)) |
                          ((uint32_t)__half_as_ushort(__float2half_rn(a1)) << 16);
        }
    }
    if (tid < TM) ccnt[tid] = 0;

    double dloss = 0.0;

    for (int q = 0; q < Q_; ++q) {
        const float* cbq = cb_all + (size_t)q * C_ * D_;
        for (int i = tid; i < C_; i += THREADS) c2s[i] = g_c2[q * C_ + i];
        __syncthreads();  // A16 (from prev fused update / initial), c2s, ccnt ready

        // prefetch chunk 0 (128 codes x 256B = 2048 x 16B units)
        {
            const __half* src0 = g_bk + (size_t)q * C_ * D_;
#pragma unroll
            for (int it = 0; it < 4; ++it) {
                int u = it * THREADS + tid;
                int code = u >> 4, blk = u & 15;
                cp16(sBB + code * ROWSTRIDE + blk * 16,
                     src0 + (size_t)code * D_ + blk * 8);
            }
            CP_COMMIT;
        }

        const float INF = __int_as_float(0x7f800000);
        float rm0 = INF, rm1 = INF;

        for (int ch = 0; ch < NCHUNK; ++ch) {
            CP_WAIT0;
            __syncthreads();

            if (ch + 1 < NCHUNK) {
                const __half* srcn = g_bk + ((size_t)q * C_ + (ch + 1) * TN) * D_;
                uint32_t dstb = sBB + ((ch + 1) & 1) * BB_BUF;
#pragma unroll
                for (int it = 0; it < 4; ++it) {
                    int u = it * THREADS + tid;
                    int code = u >> 4, blk = u & 15;
                    cp16(dstb + code * ROWSTRIDE + blk * 16,
                         srcn + (size_t)code * D_ + blk * 8);
                }
                CP_COMMIT;
            }

            const uint32_t bufB = sBB + (ch & 1) * BB_BUF;

            float c[8][4];
#pragma unroll
            for (int nt = 0; nt < 8; ++nt)
#pragma unroll
                for (int j = 0; j < 4; ++j) c[nt][j] = 0.f;

#pragma unroll
            for (int kk = 0; kk < 8; ++kk) {
                uint32_t a0[4];
                ldm4(a0[0], a0[1], a0[2], a0[3], sA16 + aoff + kk * 32);
#pragma unroll
                for (int ntp = 0; ntp < 4; ++ntp) {
                    uint32_t b0[4];
                    uint32_t bbase = bufB + boff + ntp * 16 * ROWSTRIDE + kk * 32;
                    ldm4(b0[0], b0[1], b0[2], b0[3], bbase);
                    float* cl = c[2 * ntp];
                    float* ch2 = c[2 * ntp + 1];
                    mma16816(cl[0], cl[1], cl[2], cl[3], a0[0], a0[1], a0[2], a0[3], b0[0], b0[1]);
                    mma16816(ch2[0], ch2[1], ch2[2], ch2[3], a0[0], a0[1], a0[2], a0[3], b0[2], b0[3]);
                }
            }

            // fast scores for this warp's code half
            float sc[8][4];
            float cm0 = INF, cm1 = INF;
            const int cgb = ch * TN + whalf * 64 + 2 * (lane & 3);
#pragma unroll
            for (int nt = 0; nt < 8; ++nt) {
                int cg = cgb + nt * 8;
                float c2a = c2s[cg], c2b = c2s[cg + 1];
                float s0 = fmaf(-2.f, c[nt][0], c2a);
                float s1 = fmaf(-2.f, c[nt][1], c2b);
                float s2 = fmaf(-2.f, c[nt][2], c2a);
                float s3 = fmaf(-2.f, c[nt][3], c2b);
                sc[nt][0] = s0; sc[nt][1] = s1; sc[nt][2] = s2; sc[nt][3] = s3;
                cm0 = fminf(cm0, fminf(s0, s1));
                cm1 = fminf(cm1, fminf(s2, s3));
            }
#pragma unroll
            for (int m = 1; m <= 2; m <<= 1) {
                cm0 = fminf(cm0, __shfl_xor_sync(0xffffffffu, cm0, m));
                cm1 = fminf(cm1, __shfl_xor_sync(0xffffffffu, cm1, m));
            }
            rm0 = fminf(rm0, cm0);
            rm1 = fminf(rm1, cm1);
            float th0 = rm0 + DELTA, th1 = rm1 + DELTA;

            // append candidates (guarded: most chunks contribute none)
            if (cm0 < th0) {
#pragma unroll
                for (int nt = 0; nt < 8; ++nt) {
                    int cg = cgb + nt * 8;
                    if (sc[nt][0] < th0) { int p = atomicAdd(&ccnt[R0], 1); if (p < CAP) cand[R0 * CAP + p] = (unsigned short)cg; }
                    if (sc[nt][1] < th0) { int p = atomicAdd(&ccnt[R0], 1); if (p < CAP) cand[R0 * CAP + p] = (unsigned short)(cg + 1); }
                }
            }
            if (cm1 < th1) {
#pragma unroll
                for (int nt = 0; nt < 8; ++nt) {
                    int cg = cgb + nt * 8;
                    if (sc[nt][2] < th1) { int p = atomicAdd(&ccnt[R1], 1); if (p < CAP) cand[R1 * CAP + p] = (unsigned short)cg; }
                    if (sc[nt][3] < th1) { int p = atomicAdd(&ccnt[R1], 1); if (p < CAP) cand[R1 * CAP + p] = (unsigned short)(cg + 1); }
                }
            }
        }
        __syncthreads();  // candidates visible

        // ---- exact fp32 rescore (warp set A only); lexicographic (val, idx) min ----
        if (whalf == 0) {
#pragma unroll
            for (int rr = 0; rr < 2; ++rr) {
                int r = rr ? R1 : R0;
                int n = ccnt[r];
                bool ovf = n > CAP;
                if (ovf) n = C_;  // guaranteed-correct fallback
                float bv = INF;
                int bi = 0x7fffffff;
                for (int i = lane & 3; i < n; i += 4) {
                    int code = ovf ? i : (int)cand[r * CAP + i];
                    const float4* cp4 = (const float4*)(cbq + (size_t)code * D_);
                    float s = 0.f;
#pragma unroll 8
                    for (int dq = 0; dq < 32; ++dq) {
                        float4 cv = cp4[dq];
                        s = fmaf(As[(4 * dq + 0) * 128 + r], cv.x, s);
                        s = fmaf(As[(4 * dq + 1) * 128 + r], cv.y, s);
                        s = fmaf(As[(4 * dq + 2) * 128 + r], cv.z, s);
                        s = fmaf(As[(4 * dq + 3) * 128 + r], cv.w, s);
                    }
                    float scv = fmaf(-2.f, s, c2s[code]);
                    if (scv < bv || (scv == bv && code < bi)) { bv = scv; bi = code; }
                }
#pragma unroll
                for (int m = 1; m <= 2; m <<= 1) {
                    float ov = __shfl_xor_sync(0xffffffffu, bv, m);
                    int oi = __shfl_xor_sync(0xffffffffu, bi, m);
                    if (ov < bv || (ov == bv && oi < bi)) { bv = ov; bi = oi; }
                }
                if ((lane & 3) == 0) bidx[r] = bi;
            }
        }
        __syncthreads();  // bidx ready; screening reads of A16 done

        // ---- fused: residual update + loss + fp16 convert for next q ----
        {
            const float4* cp4 =
                (const float4*)(cbq + (size_t)bidx[urow] * D_ + udbase);
            uint32_t* dst = (uint32_t*)(smem + OFF_A16 + urow * ROWSTRIDE);
            float ls = 0.f;
#pragma unroll
            for (int i = 0; i < 8; ++i) {
                float4 cv = cp4[i];
                int d = udbase + 4 * i;
                float n0 = As[(d + 0) * 128 + urow] - cv.x;
                float n1 = As[(d + 1) * 128 + urow] - cv.y;
                float n2 = As[(d + 2) * 128 + urow] - cv.z;
                float n3 = As[(d + 3) * 128 + urow] - cv.w;
                As[(d + 0) * 128 + urow] = n0;
                As[(d + 1) * 128 + urow] = n1;
                As[(d + 2) * 128 + urow] = n2;
                As[(d + 3) * 128 + urow] = n3;
                ls += n0 * n0 + n1 * n1 + n2 * n2 + n3 * n3;
                if (q + 1 < Q_) {
                    dst[(d >> 1) + 0] = (uint32_t)__half_as_ushort(__float2half_rn(n0)) |
                                        ((uint32_t)__half_as_ushort(__float2half_rn(n1)) << 16);
                    dst[(d >> 1) + 1] = (uint32_t)__half_as_ushort(__float2half_rn(n2)) |
                                        ((uint32_t)__half_as_ushort(__float2half_rn(n3)) << 16);
                }
            }
            dloss += (double)ls;
        }
        if (tid < TM) ccnt[tid] = 0;  // after rescore read, before next q
        // next q's top-of-loop __syncthreads() orders A16/As/ccnt for screening
    }

    __syncthreads();
    // quantized = x - residual_final, straight [B,D,T]
    for (int i = 0; i < 32; ++i) {
        int idx = i * THREADS + tid;
        int d = idx >> 7, tc = idx & 127;
        size_t gi = (size_t)d * T_ + tc;
        out[(size_t)b * D_ * T_ + t0 + gi] = xb[gi] - As[d * 128 + tc];
    }

    // loss reduce
    double v = dloss;
#pragma unroll
    for (int o = 16; o; o >>= 1) v += __shfl_down_sync(0xffffffffu, v, o);
    if (lane == 0) lred[w] = v;
    __syncthreads();
    if (tid == 0) {
        double tot = 0.0;
#pragma unroll
        for (int i = 0; i < 16; ++i) tot += lred[i];
        atomicAdd(&g_loss, tot);
    }
}

__global__ void k_loss(float* __restrict__ out, int out_size) {
    if (out_size > NOUT) out[NOUT] = (float)(g_loss / (double)((size_t)BT_ * D_));
}

extern "C" void kernel_launch(void* const* d_in, const int* in_sizes, int n_in,
                              void* d_out, int out_size) {
    const float* x = (const float*)d_in[0];
    const float* cb = (const float*)d_in[1];
    float* out = (float*)d_out;

    cudaFuncSetAttribute(k_vq, cudaFuncAttributeMaxDynamicSharedMemorySize, SMEM_BYTES);

    k_prep<<<Q_ * C_, 128>>>(cb);
    k_c2<<<(Q_ * C_) / 8, 256>>>(cb);
    k_vq<<<BT_ / TM, THREADS, SMEM_BYTES>>>(x, cb, out);
    k_loss<<<1, 1>>>(out, out_size);
}